// round 1
// baseline (speedup 1.0000x reference)
#include <cuda_runtime.h>
#include <cuda_bf16.h>
#include <cstdint>

// BahdanauAttention with a size-1 attention axis:
//   softmax over axis=1 (length 1) == 1.0 exactly
//   => attention_weights = ones(B,1,1)
//   => context = features  (bit-exact copy)
// The tanh/GEMM score path is mathematically dead. Kernel = 128 MiB copy + fill.

static constexpr long long Bsz = 16384;
static constexpr long long Dsz = 2048;
static constexpr long long CTX_VECS = (Bsz * Dsz) / 4;   // 8,388,608 float4
static constexpr long long AW_VECS  = Bsz / 4;           // 4,096 float4
static constexpr long long TOT_VECS = CTX_VECS + AW_VECS;

__global__ void __launch_bounds__(256)
bahdanau_copy_kernel(const float4* __restrict__ features, float4* __restrict__ out) {
    long long i = (long long)blockIdx.x * blockDim.x + threadIdx.x;
    long long stride = (long long)gridDim.x * blockDim.x;
    const float4 ones = make_float4(1.f, 1.f, 1.f, 1.f);
    for (; i < TOT_VECS; i += stride) {
        if (i < CTX_VECS) {
            out[i] = features[i];
        } else {
            out[i] = ones;
        }
    }
}

extern "C" void kernel_launch(void* const* d_in, const int* in_sizes, int n_in,
                              void* d_out, int out_size) {
    const float4* features = (const float4*)d_in[0];
    float4* out = (float4*)d_out;

    // One pass, grid sized so each thread does ~4 vectors (keeps grid modest,
    // fully saturates HBM with MLP from the unrolled grid-stride loop).
    const int threads = 256;
    long long blocks_ll = (TOT_VECS + threads - 1) / threads;   // 1-vec-per-thread
    // cap at a multiple of SM count waves; full 1:1 mapping is fine too
    int blocks = (int)((blocks_ll > 65535LL * 32LL) ? 65535LL * 32LL : blocks_ll);
    bahdanau_copy_kernel<<<blocks, threads>>>(features, out);
}